// round 2
// baseline (speedup 1.0000x reference)
#include <cuda_runtime.h>
#include <cuda_bf16.h>

// Problem constants (fixed shapes for MultiBoxLoss300)
#define NPRIORS   22536
#define NBATCH    32
#define NOBJ      16
#define NCLS      81
#define NTOTAL    (NBATCH * NPRIORS)      // 721152
#define MAIN_TPB  128
#define MAIN_BLOCKS (NTOTAL / MAIN_TPB)   // 5634 (exact)

typedef unsigned long long u64;

// Scratch (device globals; no dynamic allocation allowed)
__device__ u64    g_scr[NTOTAL];          // per-(b,prior): hi32 = float bits of ov, lo32 = obj idx
__device__ u64    g_best[NBATCH * NOBJ];  // per-(b,obj): hi32 = iou bits, lo32 = 0xFFFFFFFF - prior
__device__ double g_acc[4];               // conf_sum, n_include, loc_sum, n_pos

// ---------------------------------------------------------------------------
// Kernel 0: init accumulators + per-object argmax slots
// ---------------------------------------------------------------------------
__global__ void init_kernel() {
    int i = threadIdx.x;
    if (i < NBATCH * NOBJ) g_best[i] = 0xFFFFFFFFULL;   // pack(0.0f, idx 0)
    if (i < 4) g_acc[i] = 0.0;
}

// ---------------------------------------------------------------------------
// Kernel 1: matching. Per (b, prior): IoU against 16 boxes.
//   - row max (over objects, first-index ties)  -> g_scr
//   - column max (over priors, first-index ties) -> g_best via packed atomicMax
// fp32 op order mirrors the JAX reference exactly (IEEE div, only
// exact-product contractions) so threshold/argmax decisions cannot flip.
// ---------------------------------------------------------------------------
__global__ __launch_bounds__(256) void match_kernel(const float* __restrict__ boxes,
                                                    const float* __restrict__ priors) {
    __shared__ float4 sbox[NOBJ];
    __shared__ float  sba[NOBJ];
    __shared__ u64    smax[NOBJ];

    int b = blockIdx.y;
    int tid = threadIdx.x;
    int p = blockIdx.x * 256 + tid;

    if (tid < NOBJ) {
        float4 tb = ((const float4*)boxes)[b * NOBJ + tid];
        sbox[tid] = tb;
        sba[tid] = (tb.z - tb.x) * (tb.w - tb.y);
        smax[tid] = 0ULL;
    }
    __syncthreads();

    bool valid = (p < NPRIORS);
    int pc = valid ? p : (NPRIORS - 1);
    float4 pr = ((const float4*)priors)[pc];
    float px1 = pr.x - pr.z * 0.5f;
    float py1 = pr.y - pr.w * 0.5f;
    float px2 = pr.x + pr.z * 0.5f;
    float py2 = pr.y + pr.w * 0.5f;
    float pa = (px2 - px1) * (py2 - py1);

    float bestv = -1.0f;
    int besto = 0;

    #pragma unroll
    for (int o = 0; o < NOBJ; o++) {
        float4 tb = sbox[o];
        float iw = fmaxf(fminf(px2, tb.z) - fmaxf(px1, tb.x), 0.0f);
        float ih = fmaxf(fminf(py2, tb.w) - fmaxf(py1, tb.y), 0.0f);
        float inter = iw * ih;
        float iou = inter / ((sba[o] + pa) - inter);   // IEEE division, matches XLA
        if (valid && iou > bestv) { bestv = iou; besto = o; }  // strict > keeps first index

        // column (per-object) argmax: larger iou wins, ties -> smaller prior idx
        u64 pk = valid ? ((((u64)__float_as_uint(iou)) << 32) |
                          (u64)(0xFFFFFFFFu - (unsigned)p))
                       : 0ULL;
        #pragma unroll
        for (int off = 16; off; off >>= 1) {
            u64 other = __shfl_down_sync(0xFFFFFFFFu, pk, off);
            if (other > pk) pk = other;
        }
        if ((tid & 31) == 0) atomicMax(&smax[o], pk);
    }

    if (valid)
        g_scr[(size_t)b * NPRIORS + p] =
            (((u64)__float_as_uint(bestv)) << 32) | (unsigned)besto;

    __syncthreads();
    if (tid < NOBJ) atomicMax(&g_best[b * NOBJ + tid], smax[tid]);
}

// ---------------------------------------------------------------------------
// Kernel 2: override — each object's best prior forced to (ov=1.0, obj=o).
// Sequential ascending o per batch => last-wins on duplicate priors.
// ---------------------------------------------------------------------------
__global__ void override_kernel() {
    int b = threadIdx.x;
    if (b < NBATCH) {
        for (int o = 0; o < NOBJ; o++) {
            u64 pk = g_best[b * NOBJ + o];
            unsigned P = 0xFFFFFFFFu - (unsigned)(pk & 0xFFFFFFFFu);
            g_scr[(size_t)b * NPRIORS + P] =
                (((u64)__float_as_uint(1.0f)) << 32) | (unsigned)o;
        }
    }
}

// ---------------------------------------------------------------------------
// Kernel 3: fused focal + DIoU loss. One thread per prior; scores staged
// through shared memory with coalesced float4 loads (block tile is 16B
// aligned: blockIdx * 41472 bytes). Stride-81-word shared reads are
// bank-conflict-free (gcd(81,32)=1).
// ---------------------------------------------------------------------------
__global__ __launch_bounds__(MAIN_TPB) void fused_loss_kernel(
    const float* __restrict__ scores,
    const float* __restrict__ locs,
    const float* __restrict__ boxes,
    const int*   __restrict__ labels,
    const float* __restrict__ priors) {

    __shared__ float tile[MAIN_TPB * NCLS];
    __shared__ float rconf[MAIN_TPB / 32];
    __shared__ float rloc[MAIN_TPB / 32];
    __shared__ unsigned rcnt[MAIN_TPB / 32];

    // stage 128 priors x 81 classes
    const float4* src = (const float4*)(scores + (size_t)blockIdx.x * (MAIN_TPB * NCLS));
    float4* dst = (float4*)tile;
    #pragma unroll 8
    for (int i = threadIdx.x; i < MAIN_TPB * NCLS / 4; i += MAIN_TPB)
        dst[i] = src[i];
    __syncthreads();

    int f = blockIdx.x * MAIN_TPB + threadIdx.x;
    int b = f / NPRIORS;
    int p = f - b * NPRIORS;

    u64 pk = g_scr[f];
    float ov = __uint_as_float((unsigned)(pk >> 32));
    int obj = (int)(unsigned)(pk & 0xFFFFFFFFu);
    int lab = labels[b * NOBJ + obj];
    if (ov < 0.5f) lab = -1;
    if (ov < 0.4f) lab = 0;

    const float* s = tile + threadIdx.x * NCLS;
    float a0 = 0.f, a1 = 0.f, a2 = 0.f;
    #pragma unroll
    for (int i = 0; i < NCLS; i += 3) {
        a0 += __expf(s[i]);
        a1 += __expf(s[i + 1]);
        a2 += __expf(s[i + 2]);
    }
    float sum = (a0 + a1) + a2;

    int t = lab > 0 ? lab : 0;
    float st = s[t];
    float lse = __logf(sum);
    float logpt = st - lse;
    float pt = __expf(logpt);
    float om = 1.0f - pt;
    float focal = -(om * om) * logpt;

    float confv = 0.f, locv = 0.f;
    int inc = 0, npos = 0;
    if (lab >= 0) { confv = focal; inc = 1; }
    if (lab > 0) {
        npos = 1;
        float4 g = ((const float4*)locs)[f];
        float4 pr = ((const float4*)priors)[p];
        float cx = g.x * pr.z / 10.0f + pr.x;
        float cy = g.y * pr.w / 10.0f + pr.y;
        float w  = __expf(g.z / 5.0f) * pr.z;
        float h  = __expf(g.w / 5.0f) * pr.w;
        float px1 = cx - w * 0.5f, py1 = cy - h * 0.5f;
        float px2 = cx + w * 0.5f, py2 = cy + h * 0.5f;
        float4 tb = ((const float4*)boxes)[b * NOBJ + obj];
        float iw = fmaxf(fminf(px2, tb.z) - fmaxf(px1, tb.x), 0.0f);
        float ih = fmaxf(fminf(py2, tb.w) - fmaxf(py1, tb.y), 0.0f);
        float inter = iw * ih;
        float ap = (px2 - px1) * (py2 - py1);
        float at = (tb.z - tb.x) * (tb.w - tb.y);
        float iou = inter / ((ap + at) - inter);
        float cpx = (px1 + px2) * 0.5f, cpy = (py1 + py2) * 0.5f;
        float ctx = (tb.x + tb.z) * 0.5f, cty = (tb.y + tb.w) * 0.5f;
        float dx = cpx - ctx, dy = cpy - cty;
        float interd = dx * dx + dy * dy;
        float ox1 = fminf(px1, tb.x), oy1 = fminf(py1, tb.y);
        float ox2 = fmaxf(px2, tb.z), oy2 = fmaxf(py2, tb.w);
        float ow = fmaxf(ox2 - ox1, 0.0f), oh = fmaxf(oy2 - oy1, 0.0f);
        float outerd = ow * ow + oh * oh;
        float d = iou - interd / outerd;
        d = fminf(fmaxf(d, -1.0f), 1.0f);
        locv = 1.0f - d;
    }

    unsigned cnt = (unsigned)inc | ((unsigned)npos << 16);
    #pragma unroll
    for (int off = 16; off; off >>= 1) {
        confv += __shfl_down_sync(0xFFFFFFFFu, confv, off);
        locv  += __shfl_down_sync(0xFFFFFFFFu, locv, off);
        cnt   += __shfl_down_sync(0xFFFFFFFFu, cnt, off);
    }
    int w = threadIdx.x >> 5;
    if ((threadIdx.x & 31) == 0) { rconf[w] = confv; rloc[w] = locv; rcnt[w] = cnt; }
    __syncthreads();
    if (threadIdx.x == 0) {
        float c = 0.f, l = 0.f; unsigned k = 0;
        #pragma unroll
        for (int i = 0; i < MAIN_TPB / 32; i++) { c += rconf[i]; l += rloc[i]; k += rcnt[i]; }
        atomicAdd(&g_acc[0], (double)c);
        atomicAdd(&g_acc[1], (double)(k & 0xFFFFu));
        atomicAdd(&g_acc[2], (double)l);
        atomicAdd(&g_acc[3], (double)(k >> 16));
    }
}

// ---------------------------------------------------------------------------
// Kernel 4: finalize
// ---------------------------------------------------------------------------
__global__ void finalize_kernel(float* out) {
    double npos = g_acc[3];
    double conf = g_acc[0] / g_acc[1] / npos;
    double loc = g_acc[2] / npos;
    out[0] = (float)(conf + 25.0 * loc);
}

// ---------------------------------------------------------------------------
// Launch. Expected metadata order: predicted_locs, predicted_scores, boxes,
// labels (int32), priors_cxcy. Mapped defensively by element count (all five
// are distinct), so any harness ordering works. Output: 1 float.
// ---------------------------------------------------------------------------
extern "C" void kernel_launch(void* const* d_in, const int* in_sizes, int n_in,
                              void* d_out, int out_size) {
    const float* locs   = 0;
    const float* scores = 0;
    const float* boxes  = 0;
    const int*   labels = 0;
    const float* priors = 0;

    for (int i = 0; i < n_in; i++) {
        switch (in_sizes[i]) {
            case NTOTAL * 4:        locs   = (const float*)d_in[i]; break; // 2,884,608
            case NTOTAL * NCLS:     scores = (const float*)d_in[i]; break; // 58,413,312
            case NBATCH * NOBJ * 4: boxes  = (const float*)d_in[i]; break; // 2,048
            case NBATCH * NOBJ:     labels = (const int*)d_in[i];   break; // 512
            case NPRIORS * 4:       priors = (const float*)d_in[i]; break; // 90,144
        }
    }

    init_kernel<<<1, 512>>>();
    dim3 gA((NPRIORS + 255) / 256, NBATCH);
    match_kernel<<<gA, 256>>>(boxes, priors);
    override_kernel<<<1, 32>>>();
    fused_loss_kernel<<<MAIN_BLOCKS, MAIN_TPB>>>(scores, locs, boxes, labels, priors);
    finalize_kernel<<<1, 1>>>((float*)d_out);
}